// round 1
// baseline (speedup 1.0000x reference)
#include <cuda_runtime.h>

#define NN 50000
#define DD 128
#define EE 600000
#define GG 512
#define LLAYERS 3
#define EDIM 16
#define JKD 384
#define TILE_R 64
#define NTILES ((NN + TILE_R - 1) / TILE_R)

// Scratch (device globals: no runtime allocation allowed)
__device__ float g_xcur[NN * DD];          // 25.6 MB
__device__ float g_agg[NN * DD];           // 25.6 MB
__device__ float g_xj[(size_t)NN * JKD];   // 76.8 MB
__device__ float g_pool[GG * JKD];         // 0.79 MB

// ---------------------------------------------------------------------------
// init: x_cur = x + vn_emb[0], agg = 0
// ---------------------------------------------------------------------------
__global__ void init_kernel(const float* __restrict__ x, const float* __restrict__ vn0) {
    int i = blockIdx.x * blockDim.x + threadIdx.x;   // float4 index
    if (i >= NN * DD / 4) return;
    float4 xv = reinterpret_cast<const float4*>(x)[i];
    float4 vv = reinterpret_cast<const float4*>(vn0)[i & 31];
    xv.x += vv.x; xv.y += vv.y; xv.z += vv.z; xv.w += vv.w;
    reinterpret_cast<float4*>(g_xcur)[i] = xv;
    reinterpret_cast<float4*>(g_agg)[i] = make_float4(0.f, 0.f, 0.f, 0.f);
}

// ---------------------------------------------------------------------------
// Edge kernel: agg[dst] += relu(x[src] + edge_attr @ Wₑ + bₑ), warp per edge
// ---------------------------------------------------------------------------
__global__ __launch_bounds__(256) void edge_kernel(
    const int* __restrict__ ei, const float* __restrict__ ea,
    const float* __restrict__ ew, const float* __restrict__ ebias)
{
    __shared__ float sw[EDIM * DD];   // 8 KB
    __shared__ float sb[DD];
    for (int i = threadIdx.x; i < EDIM * DD; i += 256) sw[i] = ew[i];
    for (int i = threadIdx.x; i < DD; i += 256) sb[i] = ebias[i];
    __syncthreads();

    const int lane = threadIdx.x & 31;
    const int warp = (blockIdx.x * blockDim.x + threadIdx.x) >> 5;
    const int nw = (gridDim.x * blockDim.x) >> 5;
    const float4 bv = *reinterpret_cast<const float4*>(&sb[lane * 4]);

    for (int e = warp; e < EE; e += nw) {
        const int src = ei[e];
        const int dst = ei[EE + e];
        const float a = (lane < EDIM) ? ea[e * EDIM + lane] : 0.f;
        float4 acc = bv;
#pragma unroll
        for (int k = 0; k < EDIM; k++) {
            const float ak = __shfl_sync(0xffffffffu, a, k);
            const float4 w = *reinterpret_cast<const float4*>(&sw[k * DD + lane * 4]);
            acc.x = fmaf(ak, w.x, acc.x);
            acc.y = fmaf(ak, w.y, acc.y);
            acc.z = fmaf(ak, w.z, acc.z);
            acc.w = fmaf(ak, w.w, acc.w);
        }
        const float4 xv = *reinterpret_cast<const float4*>(&g_xcur[(size_t)src * DD + lane * 4]);
        acc.x = fmaxf(acc.x + xv.x, 0.f);
        acc.y = fmaxf(acc.y + xv.y, 0.f);
        acc.z = fmaxf(acc.z + xv.z, 0.f);
        acc.w = fmaxf(acc.w + xv.w, 0.f);
        float* p = &g_agg[(size_t)dst * DD + lane * 4];
        asm volatile("red.global.add.v4.f32 [%0], {%1,%2,%3,%4};"
                     :: "l"(p), "f"(acc.x), "f"(acc.y), "f"(acc.z), "f"(acc.w)
                     : "memory");
    }
}

// ---------------------------------------------------------------------------
// Node MLP: h=(1+eps)*x+agg; y=relu(h@W1+b1); x2=y@W2+b2
// Fused epilogue: xj[:,layer] = x2; x_cur = x2 + vn[layer+1]; agg = 0
// Persistent CTAs: weights stay in SMEM across all tiles.
// ---------------------------------------------------------------------------
__device__ __forceinline__ void tile_gemm(
    const float* sA, const float* sW, const float* __restrict__ bias,
    int c4, int rg, float4 acc[8])
{
    const float4 bvv = reinterpret_cast<const float4*>(bias)[c4];
#pragma unroll
    for (int r = 0; r < 8; r++) acc[r] = bvv;
#pragma unroll 1
    for (int k = 0; k < DD; k += 4) {
        const float4 w0 = *reinterpret_cast<const float4*>(&sW[(k + 0) * DD + c4 * 4]);
        const float4 w1 = *reinterpret_cast<const float4*>(&sW[(k + 1) * DD + c4 * 4]);
        const float4 w2 = *reinterpret_cast<const float4*>(&sW[(k + 2) * DD + c4 * 4]);
        const float4 w3 = *reinterpret_cast<const float4*>(&sW[(k + 3) * DD + c4 * 4]);
#pragma unroll
        for (int r = 0; r < 8; r++) {
            const float4 a = *reinterpret_cast<const float4*>(&sA[(rg * 8 + r) * DD + k]);
            acc[r].x = fmaf(a.x, w0.x, acc[r].x);
            acc[r].y = fmaf(a.x, w0.y, acc[r].y);
            acc[r].z = fmaf(a.x, w0.z, acc[r].z);
            acc[r].w = fmaf(a.x, w0.w, acc[r].w);
            acc[r].x = fmaf(a.y, w1.x, acc[r].x);
            acc[r].y = fmaf(a.y, w1.y, acc[r].y);
            acc[r].z = fmaf(a.y, w1.z, acc[r].z);
            acc[r].w = fmaf(a.y, w1.w, acc[r].w);
            acc[r].x = fmaf(a.z, w2.x, acc[r].x);
            acc[r].y = fmaf(a.z, w2.y, acc[r].y);
            acc[r].z = fmaf(a.z, w2.z, acc[r].z);
            acc[r].w = fmaf(a.z, w2.w, acc[r].w);
            acc[r].x = fmaf(a.w, w3.x, acc[r].x);
            acc[r].y = fmaf(a.w, w3.y, acc[r].y);
            acc[r].z = fmaf(a.w, w3.z, acc[r].z);
            acc[r].w = fmaf(a.w, w3.w, acc[r].w);
        }
    }
}

__global__ __launch_bounds__(256) void node_kernel(
    const float* __restrict__ w1, const float* __restrict__ b1,
    const float* __restrict__ w2, const float* __restrict__ b2,
    const float* __restrict__ epsp, const float* __restrict__ vn_next,
    int layer, int zero_agg)
{
    extern __shared__ float sm[];
    float* sW1 = sm;                  // 64 KB
    float* sW2 = sm + DD * DD;        // 64 KB
    float* sH  = sm + 2 * DD * DD;    // 32 KB
    float* sY  = sH + TILE_R * DD;    // 32 KB
    const int t = threadIdx.x;

    for (int i = t; i < DD * DD / 4; i += 256) {
        reinterpret_cast<float4*>(sW1)[i] = reinterpret_cast<const float4*>(w1)[i];
        reinterpret_cast<float4*>(sW2)[i] = reinterpret_cast<const float4*>(w2)[i];
    }
    const float epsv = 1.0f + *epsp;
    const int c4 = t & 31;   // column group (4 cols)
    const int rg = t >> 5;   // row group (8 rows)

    float4 vn4 = make_float4(0.f, 0.f, 0.f, 0.f);
    if (vn_next) vn4 = reinterpret_cast<const float4*>(vn_next)[c4];

    for (int tile = blockIdx.x; tile < NTILES; tile += gridDim.x) {
        const int row0 = tile * TILE_R;
        __syncthreads();   // protect sH/sY reuse; also fences weight load (iter 0)

        // h tile = (1+eps)*x + agg
        for (int i = t; i < TILE_R * DD / 4; i += 256) {
            const int row = row0 + (i >> 5);
            float4 hv = make_float4(0.f, 0.f, 0.f, 0.f);
            if (row < NN) {
                const int gi = row0 * (DD / 4) + i;
                const float4 xv = reinterpret_cast<const float4*>(g_xcur)[gi];
                const float4 av = reinterpret_cast<const float4*>(g_agg)[gi];
                hv.x = fmaf(epsv, xv.x, av.x);
                hv.y = fmaf(epsv, xv.y, av.y);
                hv.z = fmaf(epsv, xv.z, av.z);
                hv.w = fmaf(epsv, xv.w, av.w);
            }
            reinterpret_cast<float4*>(sH)[i] = hv;
        }
        __syncthreads();

        float4 acc[8];
        tile_gemm(sH, sW1, b1, c4, rg, acc);
#pragma unroll
        for (int r = 0; r < 8; r++) {
            float4 v = acc[r];
            v.x = fmaxf(v.x, 0.f); v.y = fmaxf(v.y, 0.f);
            v.z = fmaxf(v.z, 0.f); v.w = fmaxf(v.w, 0.f);
            *reinterpret_cast<float4*>(&sY[(rg * 8 + r) * DD + c4 * 4]) = v;
        }
        __syncthreads();

        tile_gemm(sY, sW2, b2, c4, rg, acc);

#pragma unroll
        for (int r = 0; r < 8; r++) {
            const int row = row0 + rg * 8 + r;
            if (row < NN) {
                float4 v = acc[r];
                reinterpret_cast<float4*>(&g_xj[(size_t)row * JKD + layer * DD])[c4] = v;
                if (vn_next) {
                    v.x += vn4.x; v.y += vn4.y; v.z += vn4.z; v.w += vn4.w;
                    reinterpret_cast<float4*>(&g_xcur[(size_t)row * DD])[c4] = v;
                }
                if (zero_agg)
                    reinterpret_cast<float4*>(&g_agg[(size_t)row * DD])[c4] =
                        make_float4(0.f, 0.f, 0.f, 0.f);
            }
        }
    }
}

// ---------------------------------------------------------------------------
// Global add pool (batch sorted, but atomics are cheap here: g fits in L2)
// ---------------------------------------------------------------------------
__global__ void zero_pool_kernel() {
    int i = blockIdx.x * blockDim.x + threadIdx.x;
    if (i < GG * JKD / 4)
        reinterpret_cast<float4*>(g_pool)[i] = make_float4(0.f, 0.f, 0.f, 0.f);
}

__global__ __launch_bounds__(256) void pool_kernel(const int* __restrict__ batch) {
    const int lane = threadIdx.x & 31;
    const int warp = (blockIdx.x * blockDim.x + threadIdx.x) >> 5;
    const int nw = (gridDim.x * blockDim.x) >> 5;
    for (int n = warp; n < NN; n += nw) {
        const int b = batch[n];
#pragma unroll
        for (int j = 0; j < 3; j++) {
            const float4 v = reinterpret_cast<const float4*>(&g_xj[(size_t)n * JKD + j * DD])[lane];
            float* p = &g_pool[b * JKD + j * DD + lane * 4];
            asm volatile("red.global.add.v4.f32 [%0], {%1,%2,%3,%4};"
                         :: "l"(p), "f"(v.x), "f"(v.y), "f"(v.z), "f"(v.w)
                         : "memory");
        }
    }
}

// ---------------------------------------------------------------------------
// Head: Linear(384->256) -> LN -> ReLU -> Linear(256->128) -> LN -> ReLU -> Linear(128->1)
// One block per graph row.
// ---------------------------------------------------------------------------
__device__ __forceinline__ float2 block_sum2(float a, float b) {
    __shared__ float2 sred[8];
    const int lane = threadIdx.x & 31, w = threadIdx.x >> 5;
#pragma unroll
    for (int o = 16; o; o >>= 1) {
        a += __shfl_down_sync(0xffffffffu, a, o);
        b += __shfl_down_sync(0xffffffffu, b, o);
    }
    if (lane == 0) sred[w] = make_float2(a, b);
    __syncthreads();
    if (w == 0) {
        float2 s = (lane < 8) ? sred[lane] : make_float2(0.f, 0.f);
#pragma unroll
        for (int o = 4; o; o >>= 1) {
            s.x += __shfl_down_sync(0xffffffffu, s.x, o);
            s.y += __shfl_down_sync(0xffffffffu, s.y, o);
        }
        if (lane == 0) sred[0] = s;
    }
    __syncthreads();
    const float2 r = sred[0];
    __syncthreads();
    return r;
}

__global__ __launch_bounds__(256) void head_kernel(
    const float* __restrict__ w1, const float* __restrict__ b1,
    const float* __restrict__ ga1, const float* __restrict__ be1,
    const float* __restrict__ w2, const float* __restrict__ b2,
    const float* __restrict__ ga2, const float* __restrict__ be2,
    const float* __restrict__ ow, const float* __restrict__ ob,
    float* __restrict__ out)
{
    __shared__ float sg[JKD];
    __shared__ float s1[256];
    const int g = blockIdx.x, t = threadIdx.x;

    for (int i = t; i < JKD; i += 256) sg[i] = g_pool[g * JKD + i];
    __syncthreads();

    // stage 1: 384 -> 256
    float acc = b1[t];
#pragma unroll 4
    for (int k = 0; k < JKD; k++) acc = fmaf(sg[k], w1[k * 256 + t], acc);
    float2 s = block_sum2(acc, acc * acc);
    float mu = s.x * (1.f / 256.f);
    float var = s.y * (1.f / 256.f) - mu * mu;
    s1[t] = fmaxf((acc - mu) * rsqrtf(var + 1e-5f) * ga1[t] + be1[t], 0.f);
    __syncthreads();

    // stage 2: 256 -> 128
    float acc2 = 0.f;
    if (t < 128) {
        acc2 = b2[t];
#pragma unroll 4
        for (int k = 0; k < 256; k++) acc2 = fmaf(s1[k], w2[k * 128 + t], acc2);
    }
    const float cva = (t < 128) ? acc2 : 0.f;
    float2 s2 = block_sum2(cva, cva * cva);
    float mu2 = s2.x * (1.f / 128.f);
    float var2 = s2.y * (1.f / 128.f) - mu2 * mu2;
    float v2 = 0.f;
    if (t < 128) v2 = fmaxf((acc2 - mu2) * rsqrtf(var2 + 1e-5f) * ga2[t] + be2[t], 0.f);

    // stage 3: 128 -> 1
    const float p = (t < 128) ? v2 * ow[t] : 0.f;
    float2 s3 = block_sum2(p, 0.f);
    if (t == 0) out[g] = s3.x + ob[0];
}

// ---------------------------------------------------------------------------
extern "C" void kernel_launch(void* const* d_in, const int* in_sizes, int n_in,
                              void* d_out, int out_size) {
    (void)in_sizes; (void)n_in; (void)out_size;
    const float* x     = (const float*)d_in[0];
    const int*   ei    = (const int*)d_in[1];
    const float* ea    = (const float*)d_in[2];
    const int*   batch = (const int*)d_in[3];
    const float* vn    = (const float*)d_in[4];
    const float* ew    = (const float*)d_in[5];
    const float* ebias = (const float*)d_in[6];
    const float* eps   = (const float*)d_in[7];
    const float* mw1   = (const float*)d_in[8];
    const float* mb1   = (const float*)d_in[9];
    const float* mw2   = (const float*)d_in[10];
    const float* mb2   = (const float*)d_in[11];
    const float* lw1   = (const float*)d_in[12];
    const float* lb1   = (const float*)d_in[13];
    const float* ln1g  = (const float*)d_in[14];
    const float* ln1b  = (const float*)d_in[15];
    const float* lw2   = (const float*)d_in[16];
    const float* lb2   = (const float*)d_in[17];
    const float* ln2g  = (const float*)d_in[18];
    const float* ln2b  = (const float*)d_in[19];
    const float* ow    = (const float*)d_in[20];
    const float* ob    = (const float*)d_in[21];
    float* out = (float*)d_out;

    int nsm = 148;
    cudaDeviceGetAttribute(&nsm, cudaDevAttrMultiProcessorCount, 0);

    const int node_smem = (2 * DD * DD + 2 * TILE_R * DD) * (int)sizeof(float); // 192 KB
    cudaFuncSetAttribute(node_kernel, cudaFuncAttributeMaxDynamicSharedMemorySize, node_smem);

    init_kernel<<<(NN * DD / 4 + 255) / 256, 256>>>(x, vn);

    for (int i = 0; i < LLAYERS; i++) {
        edge_kernel<<<nsm * 8, 256>>>(ei, ea, ew + i * EDIM * DD, ebias + i * DD);
        node_kernel<<<nsm, 256, node_smem>>>(
            mw1 + i * DD * DD, mb1 + i * DD,
            mw2 + i * DD * DD, mb2 + i * DD,
            eps + i,
            (i < LLAYERS - 1) ? (vn + (i + 1) * DD) : nullptr,
            i, (i < LLAYERS - 1) ? 1 : 0);
    }

    zero_pool_kernel<<<(GG * JKD / 4 + 255) / 256, 256>>>();
    pool_kernel<<<nsm * 8, 256>>>(batch);
    head_kernel<<<GG, 256>>>(lw1, lb1, ln1g, ln1b, lw2, lb2, ln2g, ln2b, ow, ob, out);
}

// round 2
// speedup vs baseline: 1.1111x; 1.1111x over previous
#include <cuda_runtime.h>

#define NN 50000
#define DD 128
#define EE 600000
#define GG 512
#define LLAYERS 3
#define EDIM 16
#define JKD 384
#define TILE_R 64
#define NTILES ((NN + TILE_R - 1) / TILE_R)

typedef unsigned long long u64;

// Scratch (device globals: no runtime allocation allowed)
__device__ float g_xcur[NN * DD];          // 25.6 MB
__device__ float g_agg[NN * DD];           // 25.6 MB
__device__ float g_xj[(size_t)NN * JKD];   // 76.8 MB
__device__ float g_pool[GG * JKD];         // 0.79 MB

// ---------------------------------------------------------------------------
// packed f32x2 helpers (sm_103a)
// ---------------------------------------------------------------------------
__device__ __forceinline__ u64 pack2(float x, float y) {
    u64 r; asm("mov.b64 %0, {%1, %2};" : "=l"(r) : "f"(x), "f"(y)); return r;
}
__device__ __forceinline__ float2 unpack2(u64 v) {
    float2 r; asm("mov.b64 {%0, %1}, %2;" : "=f"(r.x), "=f"(r.y) : "l"(v)); return r;
}
__device__ __forceinline__ void fma2(u64& d, u64 a, u64 b) {
    asm("fma.rn.f32x2 %0, %1, %2, %0;" : "+l"(d) : "l"(a), "l"(b));
}

// ---------------------------------------------------------------------------
// init: x_cur = x + vn_emb[0], agg = 0
// ---------------------------------------------------------------------------
__global__ void init_kernel(const float* __restrict__ x, const float* __restrict__ vn0) {
    int i = blockIdx.x * blockDim.x + threadIdx.x;   // float4 index
    if (i >= NN * DD / 4) return;
    float4 xv = reinterpret_cast<const float4*>(x)[i];
    float4 vv = reinterpret_cast<const float4*>(vn0)[i & 31];
    xv.x += vv.x; xv.y += vv.y; xv.z += vv.z; xv.w += vv.w;
    reinterpret_cast<float4*>(g_xcur)[i] = xv;
    reinterpret_cast<float4*>(g_agg)[i] = make_float4(0.f, 0.f, 0.f, 0.f);
}

// ---------------------------------------------------------------------------
// Edge kernel: agg[dst] += relu(x[src] + edge_attr @ We + be)
// warp per edge; weight slice (16 x 4 cols) in REGISTERS (no per-edge LDS);
// packed f32x2 FMAs; software-pipelined edge loop.
// ---------------------------------------------------------------------------
__global__ __launch_bounds__(256, 2) void edge_kernel(
    const int* __restrict__ ei, const float* __restrict__ ea,
    const float* __restrict__ ew, const float* __restrict__ ebias)
{
    const int lane = threadIdx.x & 31;

    // per-lane weight slice: rows 0..15, cols [lane*4, lane*4+4), as 2 packed pairs
    u64 w0[EDIM], w1[EDIM];
#pragma unroll
    for (int k = 0; k < EDIM; k++) {
        const float4 wv = *reinterpret_cast<const float4*>(&ew[k * DD + lane * 4]);
        w0[k] = pack2(wv.x, wv.y);
        w1[k] = pack2(wv.z, wv.w);
    }
    const float4 bq = *reinterpret_cast<const float4*>(&ebias[lane * 4]);
    const u64 b0 = pack2(bq.x, bq.y), b1 = pack2(bq.z, bq.w);

    const int warp = (blockIdx.x * blockDim.x + threadIdx.x) >> 5;
    const int nw = (gridDim.x * blockDim.x) >> 5;

    int e = warp;
    if (e >= EE) return;
    int src = ei[e];
    int dst = ei[EE + e];
    float a = (lane < EDIM) ? ea[e * EDIM + lane] : 0.f;
    float4 xv = *reinterpret_cast<const float4*>(&g_xcur[(size_t)src * DD + lane * 4]);

    while (true) {
        const int en = e + nw;
        const bool more = en < EE;
        int nsrc = 0, ndst = 0;
        float na = 0.f;
        if (more) {
            nsrc = ei[en];
            ndst = ei[EE + en];
            na = (lane < EDIM) ? ea[en * EDIM + lane] : 0.f;
        }

        u64 acc0 = b0, acc1 = b1;
#pragma unroll
        for (int k = 0; k < EDIM; k++) {
            const float ak = __shfl_sync(0xffffffffu, a, k);
            const u64 ak2 = pack2(ak, ak);
            fma2(acc0, ak2, w0[k]);
            fma2(acc1, ak2, w1[k]);
        }

        float4 nxv = make_float4(0.f, 0.f, 0.f, 0.f);
        if (more)
            nxv = *reinterpret_cast<const float4*>(&g_xcur[(size_t)nsrc * DD + lane * 4]);

        const float2 lo = unpack2(acc0), hi = unpack2(acc1);
        float4 m;
        m.x = fmaxf(lo.x + xv.x, 0.f);
        m.y = fmaxf(lo.y + xv.y, 0.f);
        m.z = fmaxf(hi.x + xv.z, 0.f);
        m.w = fmaxf(hi.y + xv.w, 0.f);

        float* p = &g_agg[(size_t)dst * DD + lane * 4];
        asm volatile("red.global.add.v4.f32 [%0], {%1,%2,%3,%4};"
                     :: "l"(p), "f"(m.x), "f"(m.y), "f"(m.z), "f"(m.w)
                     : "memory");

        if (!more) break;
        e = en; src = nsrc; dst = ndst; a = na; xv = nxv;
    }
}

// ---------------------------------------------------------------------------
// Node MLP with packed-f32x2 GEMMs. acc pairs adjacent output columns so the
// weight float4 is naturally two packed pairs; only the A scalar needs a dup
// (MOV on alu pipe). h=(1+eps)*x+agg; y=relu(h@W1+b1); x2=y@W2+b2.
// Fused epilogue: xj[:,layer]=x2; x_cur=x2+vn[l+1]; agg=0.
// ---------------------------------------------------------------------------
__device__ __forceinline__ void tile_gemm2(
    const float* sA, const float* sW, const float* __restrict__ bias,
    int c4, int rg, u64 acc0[8], u64 acc1[8])
{
    const float4 bv = reinterpret_cast<const float4*>(bias)[c4];
    const u64 bp0 = pack2(bv.x, bv.y), bp1 = pack2(bv.z, bv.w);
#pragma unroll
    for (int r = 0; r < 8; r++) { acc0[r] = bp0; acc1[r] = bp1; }

#pragma unroll 1
    for (int k = 0; k < DD; k += 4) {
        const float4 wq0 = *reinterpret_cast<const float4*>(&sW[(k + 0) * DD + c4 * 4]);
        const float4 wq1 = *reinterpret_cast<const float4*>(&sW[(k + 1) * DD + c4 * 4]);
        const float4 wq2 = *reinterpret_cast<const float4*>(&sW[(k + 2) * DD + c4 * 4]);
        const float4 wq3 = *reinterpret_cast<const float4*>(&sW[(k + 3) * DD + c4 * 4]);
        const u64 w00 = pack2(wq0.x, wq0.y), w01 = pack2(wq0.z, wq0.w);
        const u64 w10 = pack2(wq1.x, wq1.y), w11 = pack2(wq1.z, wq1.w);
        const u64 w20 = pack2(wq2.x, wq2.y), w21 = pack2(wq2.z, wq2.w);
        const u64 w30 = pack2(wq3.x, wq3.y), w31 = pack2(wq3.z, wq3.w);
#pragma unroll
        for (int r = 0; r < 8; r++) {
            const float4 a = *reinterpret_cast<const float4*>(&sA[(rg * 8 + r) * DD + k]);
            const u64 ax = pack2(a.x, a.x);
            fma2(acc0[r], ax, w00); fma2(acc1[r], ax, w01);
            const u64 ay = pack2(a.y, a.y);
            fma2(acc0[r], ay, w10); fma2(acc1[r], ay, w11);
            const u64 az = pack2(a.z, a.z);
            fma2(acc0[r], az, w20); fma2(acc1[r], az, w21);
            const u64 aw = pack2(a.w, a.w);
            fma2(acc0[r], aw, w30); fma2(acc1[r], aw, w31);
        }
    }
}

__global__ __launch_bounds__(256) void node_kernel(
    const float* __restrict__ w1, const float* __restrict__ b1,
    const float* __restrict__ w2, const float* __restrict__ b2,
    const float* __restrict__ epsp, const float* __restrict__ vn_next,
    int layer, int zero_agg)
{
    extern __shared__ float sm[];
    float* sW1 = sm;                  // 64 KB
    float* sW2 = sm + DD * DD;        // 64 KB
    float* sH  = sm + 2 * DD * DD;    // 32 KB
    float* sY  = sH + TILE_R * DD;    // 32 KB
    const int t = threadIdx.x;

    for (int i = t; i < DD * DD / 4; i += 256) {
        reinterpret_cast<float4*>(sW1)[i] = reinterpret_cast<const float4*>(w1)[i];
        reinterpret_cast<float4*>(sW2)[i] = reinterpret_cast<const float4*>(w2)[i];
    }
    const float epsv = 1.0f + *epsp;
    const int c4 = t & 31;   // column group (4 cols = 2 packed pairs)
    const int rg = t >> 5;   // row group (8 rows)

    float4 vn4 = make_float4(0.f, 0.f, 0.f, 0.f);
    if (vn_next) vn4 = reinterpret_cast<const float4*>(vn_next)[c4];

    for (int tile = blockIdx.x; tile < NTILES; tile += gridDim.x) {
        const int row0 = tile * TILE_R;
        __syncthreads();   // protect sH/sY reuse; also fences weight load (iter 0)

        // h tile = (1+eps)*x + agg
        for (int i = t; i < TILE_R * DD / 4; i += 256) {
            const int row = row0 + (i >> 5);
            float4 hv = make_float4(0.f, 0.f, 0.f, 0.f);
            if (row < NN) {
                const int gi = row0 * (DD / 4) + i;
                const float4 xv = reinterpret_cast<const float4*>(g_xcur)[gi];
                const float4 av = reinterpret_cast<const float4*>(g_agg)[gi];
                hv.x = fmaf(epsv, xv.x, av.x);
                hv.y = fmaf(epsv, xv.y, av.y);
                hv.z = fmaf(epsv, xv.z, av.z);
                hv.w = fmaf(epsv, xv.w, av.w);
            }
            reinterpret_cast<float4*>(sH)[i] = hv;
        }
        __syncthreads();

        u64 acc0[8], acc1[8];
        tile_gemm2(sH, sW1, b1, c4, rg, acc0, acc1);
#pragma unroll
        for (int r = 0; r < 8; r++) {
            const float2 lo = unpack2(acc0[r]), hi = unpack2(acc1[r]);
            float4 v;
            v.x = fmaxf(lo.x, 0.f); v.y = fmaxf(lo.y, 0.f);
            v.z = fmaxf(hi.x, 0.f); v.w = fmaxf(hi.y, 0.f);
            *reinterpret_cast<float4*>(&sY[(rg * 8 + r) * DD + c4 * 4]) = v;
        }
        __syncthreads();

        tile_gemm2(sY, sW2, b2, c4, rg, acc0, acc1);

#pragma unroll
        for (int r = 0; r < 8; r++) {
            const int row = row0 + rg * 8 + r;
            if (row < NN) {
                const float2 lo = unpack2(acc0[r]), hi = unpack2(acc1[r]);
                float4 v = make_float4(lo.x, lo.y, hi.x, hi.y);
                reinterpret_cast<float4*>(&g_xj[(size_t)row * JKD + layer * DD])[c4] = v;
                if (vn_next) {
                    v.x += vn4.x; v.y += vn4.y; v.z += vn4.z; v.w += vn4.w;
                    reinterpret_cast<float4*>(&g_xcur[(size_t)row * DD])[c4] = v;
                }
                if (zero_agg)
                    reinterpret_cast<float4*>(&g_agg[(size_t)row * DD])[c4] =
                        make_float4(0.f, 0.f, 0.f, 0.f);
            }
        }
    }
}

// ---------------------------------------------------------------------------
// Global add pool
// ---------------------------------------------------------------------------
__global__ void zero_pool_kernel() {
    int i = blockIdx.x * blockDim.x + threadIdx.x;
    if (i < GG * JKD / 4)
        reinterpret_cast<float4*>(g_pool)[i] = make_float4(0.f, 0.f, 0.f, 0.f);
}

__global__ __launch_bounds__(256) void pool_kernel(const int* __restrict__ batch) {
    const int lane = threadIdx.x & 31;
    const int warp = (blockIdx.x * blockDim.x + threadIdx.x) >> 5;
    const int nw = (gridDim.x * blockDim.x) >> 5;
    for (int n = warp; n < NN; n += nw) {
        const int b = batch[n];
#pragma unroll
        for (int j = 0; j < 3; j++) {
            const float4 v = reinterpret_cast<const float4*>(&g_xj[(size_t)n * JKD + j * DD])[lane];
            float* p = &g_pool[b * JKD + j * DD + lane * 4];
            asm volatile("red.global.add.v4.f32 [%0], {%1,%2,%3,%4};"
                         :: "l"(p), "f"(v.x), "f"(v.y), "f"(v.z), "f"(v.w)
                         : "memory");
        }
    }
}

// ---------------------------------------------------------------------------
// Head: Linear(384->256) -> LN -> ReLU -> Linear(256->128) -> LN -> ReLU -> Linear(128->1)
// ---------------------------------------------------------------------------
__device__ __forceinline__ float2 block_sum2(float a, float b) {
    __shared__ float2 sred[8];
    const int lane = threadIdx.x & 31, w = threadIdx.x >> 5;
#pragma unroll
    for (int o = 16; o; o >>= 1) {
        a += __shfl_down_sync(0xffffffffu, a, o);
        b += __shfl_down_sync(0xffffffffu, b, o);
    }
    if (lane == 0) sred[w] = make_float2(a, b);
    __syncthreads();
    if (w == 0) {
        float2 s = (lane < 8) ? sred[lane] : make_float2(0.f, 0.f);
#pragma unroll
        for (int o = 4; o; o >>= 1) {
            s.x += __shfl_down_sync(0xffffffffu, s.x, o);
            s.y += __shfl_down_sync(0xffffffffu, s.y, o);
        }
        if (lane == 0) sred[0] = s;
    }
    __syncthreads();
    const float2 r = sred[0];
    __syncthreads();
    return r;
}

__global__ __launch_bounds__(256) void head_kernel(
    const float* __restrict__ w1, const float* __restrict__ b1,
    const float* __restrict__ ga1, const float* __restrict__ be1,
    const float* __restrict__ w2, const float* __restrict__ b2,
    const float* __restrict__ ga2, const float* __restrict__ be2,
    const float* __restrict__ ow, const float* __restrict__ ob,
    float* __restrict__ out)
{
    __shared__ float sg[JKD];
    __shared__ float s1[256];
    const int g = blockIdx.x, t = threadIdx.x;

    for (int i = t; i < JKD; i += 256) sg[i] = g_pool[g * JKD + i];
    __syncthreads();

    // stage 1: 384 -> 256
    float acc = b1[t];
#pragma unroll 4
    for (int k = 0; k < JKD; k++) acc = fmaf(sg[k], w1[k * 256 + t], acc);
    float2 s = block_sum2(acc, acc * acc);
    float mu = s.x * (1.f / 256.f);
    float var = s.y * (1.f / 256.f) - mu * mu;
    s1[t] = fmaxf((acc - mu) * rsqrtf(var + 1e-5f) * ga1[t] + be1[t], 0.f);
    __syncthreads();

    // stage 2: 256 -> 128
    float acc2 = 0.f;
    if (t < 128) {
        acc2 = b2[t];
#pragma unroll 4
        for (int k = 0; k < 256; k++) acc2 = fmaf(s1[k], w2[k * 128 + t], acc2);
    }
    const float cva = (t < 128) ? acc2 : 0.f;
    float2 s2 = block_sum2(cva, cva * cva);
    float mu2 = s2.x * (1.f / 128.f);
    float var2 = s2.y * (1.f / 128.f) - mu2 * mu2;
    float v2 = 0.f;
    if (t < 128) v2 = fmaxf((acc2 - mu2) * rsqrtf(var2 + 1e-5f) * ga2[t] + be2[t], 0.f);

    // stage 3: 128 -> 1
    const float p = (t < 128) ? v2 * ow[t] : 0.f;
    float2 s3 = block_sum2(p, 0.f);
    if (t == 0) out[g] = s3.x + ob[0];
}

// ---------------------------------------------------------------------------
extern "C" void kernel_launch(void* const* d_in, const int* in_sizes, int n_in,
                              void* d_out, int out_size) {
    (void)in_sizes; (void)n_in; (void)out_size;
    const float* x     = (const float*)d_in[0];
    const int*   ei    = (const int*)d_in[1];
    const float* ea    = (const float*)d_in[2];
    const int*   batch = (const int*)d_in[3];
    const float* vn    = (const float*)d_in[4];
    const float* ew    = (const float*)d_in[5];
    const float* ebias = (const float*)d_in[6];
    const float* eps   = (const float*)d_in[7];
    const float* mw1   = (const float*)d_in[8];
    const float* mb1   = (const float*)d_in[9];
    const float* mw2   = (const float*)d_in[10];
    const float* mb2   = (const float*)d_in[11];
    const float* lw1   = (const float*)d_in[12];
    const float* lb1   = (const float*)d_in[13];
    const float* ln1g  = (const float*)d_in[14];
    const float* ln1b  = (const float*)d_in[15];
    const float* lw2   = (const float*)d_in[16];
    const float* lb2   = (const float*)d_in[17];
    const float* ln2g  = (const float*)d_in[18];
    const float* ln2b  = (const float*)d_in[19];
    const float* ow    = (const float*)d_in[20];
    const float* ob    = (const float*)d_in[21];
    float* out = (float*)d_out;

    int nsm = 148;
    cudaDeviceGetAttribute(&nsm, cudaDevAttrMultiProcessorCount, 0);

    const int node_smem = (2 * DD * DD + 2 * TILE_R * DD) * (int)sizeof(float); // 192 KB
    cudaFuncSetAttribute(node_kernel, cudaFuncAttributeMaxDynamicSharedMemorySize, node_smem);

    init_kernel<<<(NN * DD / 4 + 255) / 256, 256>>>(x, vn);

    for (int i = 0; i < LLAYERS; i++) {
        edge_kernel<<<nsm * 2, 256>>>(ei, ea, ew + i * EDIM * DD, ebias + i * DD);
        node_kernel<<<nsm, 256, node_smem>>>(
            mw1 + i * DD * DD, mb1 + i * DD,
            mw2 + i * DD * DD, mb2 + i * DD,
            eps + i,
            (i < LLAYERS - 1) ? (vn + (i + 1) * DD) : nullptr,
            i, (i < LLAYERS - 1) ? 1 : 0);
    }

    zero_pool_kernel<<<(GG * JKD / 4 + 255) / 256, 256>>>();
    pool_kernel<<<nsm * 8, 256>>>(batch);
    head_kernel<<<GG, 256>>>(lw1, lb1, ln1g, ln1b, lw2, lb2, ln2g, ln2b, ow, ob, out);
}